// round 1
// baseline (speedup 1.0000x reference)
#include <cuda_runtime.h>
#include <cuda_bf16.h>

// Problem constants
#define B_   4
#define N_   2048
#define C_   256
#define H_   8
#define HD_  32
#define M_   (B_ * N_)          // 8192 rows
#define QKV_OUT (3 * C_)        // 768
#define SCALE 0.17677669529663687f  // 1/sqrt(32)

// Scratch: q,k,v,attn_out each (B,H,N,HD) = 2,097,152 floats (8 MB)
#define ELEMS (B_ * H_ * N_ * HD_)
__device__ float g_q[ELEMS];
__device__ float g_k[ELEMS];
__device__ float g_v[ELEMS];
__device__ float g_att[ELEMS];

// ---------------------------------------------------------------------------
// Kernel 1: QKV GEMM.  out[m,o] = sum_c x[m,c]*qkv_w[o,c] + qkv_b[o]
// scatter into g_q/g_k/g_v with (B,H,N,HD) layout; scale folded into q.
// Tiles: BM=64, BN=64, BK=16; 256 threads; 4x4 micro-tile per thread.
// ---------------------------------------------------------------------------
#define BM 64
#define BN 64
#define BK 16

__global__ __launch_bounds__(256) void qkv_gemm_kernel(
    const float* __restrict__ x,      // (M_, 256)
    const float* __restrict__ w,      // (768, 256)
    const float* __restrict__ bias)   // (768,)
{
    __shared__ float As[BM][BK + 1];
    __shared__ float Bs[BN][BK + 1];

    const int m0 = blockIdx.y * BM;
    const int n0 = blockIdx.x * BN;
    const int tid = threadIdx.x;
    const int tr = tid >> 4;          // 0..15
    const int tc = tid & 15;          // 0..15

    float acc[4][4];
#pragma unroll
    for (int i = 0; i < 4; i++)
#pragma unroll
        for (int j = 0; j < 4; j++) acc[i][j] = 0.f;

    const int lrow = tid >> 2;        // 0..63
    const int lc4  = (tid & 3) * 4;   // 0,4,8,12

    for (int k0 = 0; k0 < C_; k0 += BK) {
        float4 a = *(const float4*)&x[(m0 + lrow) * C_ + k0 + lc4];
        As[lrow][lc4 + 0] = a.x; As[lrow][lc4 + 1] = a.y;
        As[lrow][lc4 + 2] = a.z; As[lrow][lc4 + 3] = a.w;
        float4 b = *(const float4*)&w[(n0 + lrow) * C_ + k0 + lc4];
        Bs[lrow][lc4 + 0] = b.x; Bs[lrow][lc4 + 1] = b.y;
        Bs[lrow][lc4 + 2] = b.z; Bs[lrow][lc4 + 3] = b.w;
        __syncthreads();

#pragma unroll
        for (int kk = 0; kk < BK; kk++) {
            float ra[4], rb[4];
#pragma unroll
            for (int i = 0; i < 4; i++) ra[i] = As[tr * 4 + i][kk];
#pragma unroll
            for (int j = 0; j < 4; j++) rb[j] = Bs[tc * 4 + j][kk];
#pragma unroll
            for (int i = 0; i < 4; i++)
#pragma unroll
                for (int j = 0; j < 4; j++) acc[i][j] += ra[i] * rb[j];
        }
        __syncthreads();
    }

#pragma unroll
    for (int i = 0; i < 4; i++) {
        const int m = m0 + tr * 4 + i;
        const int bb = m >> 11;          // m / 2048
        const int n  = m & (N_ - 1);
#pragma unroll
        for (int j = 0; j < 4; j++) {
            const int o = n0 + tc * 4 + j;
            float val = acc[i][j] + bias[o];
            const int which = o >> 8;       // 0=q 1=k 2=v
            const int h = (o >> 5) & 7;
            const int d = o & 31;
            const int idx = (((bb * H_ + h) * N_) + n) * HD_ + d;
            if (which == 0)      g_q[idx] = val * SCALE;
            else if (which == 1) g_k[idx] = val;
            else                 g_v[idx] = val;
        }
    }
}

// ---------------------------------------------------------------------------
// Kernel 2: flash attention. One block = (b,h) x 128 query rows.
// Each thread owns one query row: Q, O in registers (8 float4 each).
// KV tiles of 64 rows staged in shared memory. Online softmax.
// Bias: b7[qrow%7][krow%7] from a 49-entry smem LUT.
// ---------------------------------------------------------------------------
#define QT 128
#define KT 64

__global__ __launch_bounds__(QT) void attn_kernel(
    const float* __restrict__ bt)     // bias_table (104,), only [0..12] used
{
    __shared__ float Ks[KT][HD_];
    __shared__ float Vs[KT][HD_];
    __shared__ float b7[49];

    const int bh = blockIdx.y;                // 0..31  (b*H + h)
    const int q0 = blockIdx.x * QT;
    const int tid = threadIdx.x;

    if (tid < 49) b7[tid] = bt[(tid / 7) - (tid % 7) + 6];

    const int qrow = q0 + tid;
    const long base = (long)bh * N_;
    const float* qp = g_q + (base + qrow) * HD_;

    float4 Q[8];
#pragma unroll
    for (int i = 0; i < 8; i++) Q[i] = *(const float4*)&qp[i * 4];

    float4 O[8];
#pragma unroll
    for (int i = 0; i < 8; i++) O[i] = make_float4(0.f, 0.f, 0.f, 0.f);
    float mmax = -1e30f, l = 0.f;
    const int qm7 = (qrow % 7) * 7;

    __syncthreads();  // b7 ready

    for (int t = 0; t < N_; t += KT) {
        // stage K,V tiles (each 64x32 floats = 512 float4; 128 thr x 4)
#pragma unroll
        for (int f = 0; f < 4; f++) {
            const int lin = f * 128 + tid;
            const int row = lin >> 3;
            const int c4  = (lin & 7) * 4;
            *(float4*)&Ks[row][c4] = *(const float4*)&g_k[(base + t + row) * HD_ + c4];
            *(float4*)&Vs[row][c4] = *(const float4*)&g_v[(base + t + row) * HD_ + c4];
        }
        __syncthreads();

        int km = t % 7;
#pragma unroll 2
        for (int j = 0; j < KT; j++) {
            const float4* kr = (const float4*)Ks[j];
            float s0 = 0.f, s1 = 0.f;
#pragma unroll
            for (int i = 0; i < 8; i += 2) {
                float4 ka = kr[i], kb = kr[i + 1];
                s0 += Q[i].x * ka.x + Q[i].y * ka.y + Q[i].z * ka.z + Q[i].w * ka.w;
                s1 += Q[i+1].x * kb.x + Q[i+1].y * kb.y + Q[i+1].z * kb.z + Q[i+1].w * kb.w;
            }
            float s = s0 + s1 + b7[qm7 + km];
            km++; if (km == 7) km = 0;

            float p;
            if (s > mmax) {
                const float corr = __expf(mmax - s);
                mmax = s;
                l *= corr;
#pragma unroll
                for (int i = 0; i < 8; i++) {
                    O[i].x *= corr; O[i].y *= corr; O[i].z *= corr; O[i].w *= corr;
                }
                p = 1.f;
            } else {
                p = __expf(s - mmax);
            }
            l += p;

            const float4* vr = (const float4*)Vs[j];
#pragma unroll
            for (int i = 0; i < 8; i++) {
                float4 vv = vr[i];
                O[i].x += p * vv.x; O[i].y += p * vv.y;
                O[i].z += p * vv.z; O[i].w += p * vv.w;
            }
        }
        __syncthreads();
    }

    const float inv = 1.f / l;
    float* op = g_att + (base + qrow) * HD_;
#pragma unroll
    for (int i = 0; i < 8; i++) {
        float4 o = O[i];
        o.x *= inv; o.y *= inv; o.z *= inv; o.w *= inv;
        *(float4*)&op[i * 4] = o;
    }
}

// ---------------------------------------------------------------------------
// Kernel 3: output projection.  out[m,o] = sum_c A[m,c]*proj_w[o,c] + proj_b[o]
// A[m,c] gathered from g_att: c = h*32+d -> g_att[((b*8+h)*2048+n)*32+d]
// ---------------------------------------------------------------------------
__global__ __launch_bounds__(256) void proj_gemm_kernel(
    const float* __restrict__ w,      // (256, 256)
    const float* __restrict__ bias,   // (256,)
    float* __restrict__ out)          // (M_, 256)
{
    __shared__ float As[BM][BK + 1];
    __shared__ float Bs[BN][BK + 1];

    const int m0 = blockIdx.y * BM;
    const int n0 = blockIdx.x * BN;
    const int tid = threadIdx.x;
    const int tr = tid >> 4;
    const int tc = tid & 15;

    float acc[4][4];
#pragma unroll
    for (int i = 0; i < 4; i++)
#pragma unroll
        for (int j = 0; j < 4; j++) acc[i][j] = 0.f;

    const int lrow = tid >> 2;
    const int lc4  = (tid & 3) * 4;

    for (int k0 = 0; k0 < C_; k0 += BK) {
        const int m = m0 + lrow;
        const int bb = m >> 11;
        const int n  = m & (N_ - 1);
        const int c  = k0 + lc4;        // within one 32-wide head chunk (BK=16)
        const int h  = c >> 5;
        const int d  = c & 31;
        float4 a = *(const float4*)&g_att[(((bb * H_ + h) * N_) + n) * HD_ + d];
        As[lrow][lc4 + 0] = a.x; As[lrow][lc4 + 1] = a.y;
        As[lrow][lc4 + 2] = a.z; As[lrow][lc4 + 3] = a.w;
        float4 b = *(const float4*)&w[(n0 + lrow) * C_ + k0 + lc4];
        Bs[lrow][lc4 + 0] = b.x; Bs[lrow][lc4 + 1] = b.y;
        Bs[lrow][lc4 + 2] = b.z; Bs[lrow][lc4 + 3] = b.w;
        __syncthreads();

#pragma unroll
        for (int kk = 0; kk < BK; kk++) {
            float ra[4], rb[4];
#pragma unroll
            for (int i = 0; i < 4; i++) ra[i] = As[tr * 4 + i][kk];
#pragma unroll
            for (int j = 0; j < 4; j++) rb[j] = Bs[tc * 4 + j][kk];
#pragma unroll
            for (int i = 0; i < 4; i++)
#pragma unroll
                for (int j = 0; j < 4; j++) acc[i][j] += ra[i] * rb[j];
        }
        __syncthreads();
    }

#pragma unroll
    for (int i = 0; i < 4; i++) {
        const int m = m0 + tr * 4 + i;
#pragma unroll
        for (int j = 0; j < 4; j++) {
            const int o = n0 + tc * 4 + j;
            out[m * C_ + o] = acc[i][j] + bias[o];
        }
    }
}

// ---------------------------------------------------------------------------
// Launch
// ---------------------------------------------------------------------------
extern "C" void kernel_launch(void* const* d_in, const int* in_sizes, int n_in,
                              void* d_out, int out_size)
{
    const float* x      = (const float*)d_in[0];   // (4,2048,256)
    const float* qkv_w  = (const float*)d_in[1];   // (768,256)
    const float* qkv_b  = (const float*)d_in[2];   // (768,)
    const float* proj_w = (const float*)d_in[3];   // (256,256)
    const float* proj_b = (const float*)d_in[4];   // (256,)
    const float* btab   = (const float*)d_in[5];   // (104,)
    float* out = (float*)d_out;                    // (4,2048,256)

    (void)in_sizes; (void)n_in; (void)out_size;

    dim3 g1(QKV_OUT / BN, M_ / BM);        // (12, 128)
    qkv_gemm_kernel<<<g1, 256>>>(x, qkv_w, qkv_b);

    dim3 g2(N_ / QT, B_ * H_);             // (16, 32)
    attn_kernel<<<g2, QT>>>(btab);

    dim3 g3(C_ / BN, M_ / BM);             // (4, 128)
    proj_gemm_kernel<<<g3, 256>>>(proj_w, proj_b, out);
}

// round 3
// speedup vs baseline: 3.3874x; 3.3874x over previous
#include <cuda_runtime.h>
#include <cuda_fp16.h>
#include <cstdint>

// ---------------------------------------------------------------------------
// Problem constants
// ---------------------------------------------------------------------------
#define B_   4
#define N_   2048
#define C_   256
#define H_   8
#define HD_  32
#define M_   (B_ * N_)          // 8192
#define QKV_OUT (3 * C_)        // 768
#define SCALE 0.17677669529663687f  // 1/sqrt(32)
#define ELEMS (B_ * H_ * N_ * HD_)  // 2,097,152

__device__ __half g_qh[ELEMS];
__device__ __half g_kh[ELEMS];
__device__ __half g_vh[ELEMS];
__device__ float  g_att[ELEMS];

// ---------------------------------------------------------------------------
// helpers
// ---------------------------------------------------------------------------
__device__ __forceinline__ uint32_t smem_u32(const void* p) {
    uint32_t a;
    asm("{ .reg .u64 t; cvta.to.shared.u64 t, %1; cvt.u32.u64 %0, t; }"
        : "=r"(a) : "l"(p));
    return a;
}

__device__ __forceinline__ void ldmx4(uint32_t* r, uint32_t addr) {
    asm volatile("ldmatrix.sync.aligned.m8n8.x4.shared.b16 {%0,%1,%2,%3}, [%4];"
        : "=r"(r[0]), "=r"(r[1]), "=r"(r[2]), "=r"(r[3]) : "r"(addr));
}
__device__ __forceinline__ void ldmx4t(uint32_t* r, uint32_t addr) {
    asm volatile("ldmatrix.sync.aligned.m8n8.x4.trans.shared.b16 {%0,%1,%2,%3}, [%4];"
        : "=r"(r[0]), "=r"(r[1]), "=r"(r[2]), "=r"(r[3]) : "r"(addr));
}
__device__ __forceinline__ void mma16816(float* d,
    uint32_t a0, uint32_t a1, uint32_t a2, uint32_t a3,
    uint32_t b0, uint32_t b1) {
    asm volatile("mma.sync.aligned.m16n8k16.row.col.f32.f16.f16.f32 "
        "{%0,%1,%2,%3}, {%4,%5,%6,%7}, {%8,%9}, {%0,%1,%2,%3};"
        : "+f"(d[0]), "+f"(d[1]), "+f"(d[2]), "+f"(d[3])
        : "r"(a0), "r"(a1), "r"(a2), "r"(a3), "r"(b0), "r"(b1));
}

// ---------------------------------------------------------------------------
// Kernel 1: QKV GEMM (fp32 compute, fp16 scatter into q/k/v; scale into q)
// ---------------------------------------------------------------------------
#define BM 64
#define BN 64
#define BK 16

__global__ __launch_bounds__(256) void qkv_gemm_kernel(
    const float* __restrict__ x, const float* __restrict__ w,
    const float* __restrict__ bias)
{
    __shared__ float As[BM][BK + 1];
    __shared__ float Bs[BN][BK + 1];

    const int m0 = blockIdx.y * BM;
    const int n0 = blockIdx.x * BN;
    const int tid = threadIdx.x;
    const int tr = tid >> 4;
    const int tc = tid & 15;

    float acc[4][4];
#pragma unroll
    for (int i = 0; i < 4; i++)
#pragma unroll
        for (int j = 0; j < 4; j++) acc[i][j] = 0.f;

    const int lrow = tid >> 2;
    const int lc4  = (tid & 3) * 4;

    for (int k0 = 0; k0 < C_; k0 += BK) {
        float4 a = *(const float4*)&x[(m0 + lrow) * C_ + k0 + lc4];
        As[lrow][lc4 + 0] = a.x; As[lrow][lc4 + 1] = a.y;
        As[lrow][lc4 + 2] = a.z; As[lrow][lc4 + 3] = a.w;
        float4 b = *(const float4*)&w[(n0 + lrow) * C_ + k0 + lc4];
        Bs[lrow][lc4 + 0] = b.x; Bs[lrow][lc4 + 1] = b.y;
        Bs[lrow][lc4 + 2] = b.z; Bs[lrow][lc4 + 3] = b.w;
        __syncthreads();

#pragma unroll
        for (int kk = 0; kk < BK; kk++) {
            float ra[4], rb[4];
#pragma unroll
            for (int i = 0; i < 4; i++) ra[i] = As[tr * 4 + i][kk];
#pragma unroll
            for (int j = 0; j < 4; j++) rb[j] = Bs[tc * 4 + j][kk];
#pragma unroll
            for (int i = 0; i < 4; i++)
#pragma unroll
                for (int j = 0; j < 4; j++) acc[i][j] += ra[i] * rb[j];
        }
        __syncthreads();
    }

#pragma unroll
    for (int i = 0; i < 4; i++) {
        const int m = m0 + tr * 4 + i;
        const int bb = m >> 11;
        const int n  = m & (N_ - 1);
#pragma unroll
        for (int j = 0; j < 4; j++) {
            const int o = n0 + tc * 4 + j;
            float val = acc[i][j] + bias[o];
            const int which = o >> 8;
            const int h = (o >> 5) & 7;
            const int d = o & 31;
            const int idx = (((bb * H_ + h) * N_) + n) * HD_ + d;
            if (which == 0)      g_qh[idx] = __float2half(val * SCALE);
            else if (which == 1) g_kh[idx] = __float2half(val);
            else                 g_vh[idx] = __float2half(val);
        }
    }
}

// ---------------------------------------------------------------------------
// Kernel 2: mma.sync fp16 flash attention.
//   CTA = 4 warps, 64 query rows (16 per warp). Tiles of 64 keys.
//   SMEM K/V tiles rows padded to 80B (conflict-free ldmatrix).
// ---------------------------------------------------------------------------
#define KT 64
#define ROWP 40   // halfs per smem row (80 bytes)

__global__ __launch_bounds__(128) void attn_mma_kernel(const float* __restrict__ bt)
{
    __shared__ __half Ks[KT][ROWP];
    __shared__ __half Vs[KT][ROWP];
    __shared__ float b7s[49];

    const int tid  = threadIdx.x;
    const int lane = tid & 31;
    const int warp = tid >> 5;
    const int bh = blockIdx.y;
    const int q0 = blockIdx.x * 64;
    const long base = (long)bh * N_;

    if (tid < 49) b7s[tid] = bt[(tid / 7) - (tid % 7) + 6];

    const uint32_t ks_base = smem_u32(&Ks[0][0]);
    const uint32_t vs_base = smem_u32(&Vs[0][0]);

    const int r  = lane >> 2;          // 0..7
    const int cq = lane & 3;           // 0..3
    const int c2 = cq * 2;
    const int qrowA = q0 + warp * 16 + r;
    const int qrowB = qrowA + 8;

    // Q A-fragments (held in registers for the whole kernel)
    uint32_t qf[8];
    {
        const uint32_t* qpA = (const uint32_t*)(g_qh + (base + qrowA) * HD_);
        const uint32_t* qpB = (const uint32_t*)(g_qh + (base + qrowB) * HD_);
        qf[0] = qpA[cq];      qf[1] = qpB[cq];
        qf[2] = qpA[cq + 4];  qf[3] = qpB[cq + 4];
        qf[4] = qpA[cq + 8];  qf[5] = qpB[cq + 8];
        qf[6] = qpA[cq + 12]; qf[7] = qpB[cq + 12];
    }

    const int qa7 = (qrowA % 7) * 7;
    const int qb7 = (qrowB % 7) * 7;

    float oacc[4][4];
#pragma unroll
    for (int n = 0; n < 4; n++)
#pragma unroll
        for (int i = 0; i < 4; i++) oacc[n][i] = 0.f;
    float lA = 0.f, lB = 0.f;

    // staging indices: 128 threads, 64 rows x 2 halves of 16B... (32B each)
    const int sj = tid >> 1;           // row 0..63
    const int sh = tid & 1;            // which 16-half chunk

    for (int t = 0; t < N_; t += KT) {
        __syncthreads();   // previous compute done before overwrite
        {
            const uint4* kp = (const uint4*)(g_kh + (base + t + sj) * HD_);
            const uint4* vp = (const uint4*)(g_vh + (base + t + sj) * HD_);
            *(uint4*)&Ks[sj][sh * 16 + 0] = kp[sh * 2 + 0];
            *(uint4*)&Ks[sj][sh * 16 + 8] = kp[sh * 2 + 1];
            *(uint4*)&Vs[sj][sh * 16 + 0] = vp[sh * 2 + 0];
            *(uint4*)&Vs[sj][sh * 16 + 8] = vp[sh * 2 + 1];
        }
        __syncthreads();

        // ---- S = Q @ K^T : 8 j-tiles of 16x8
        float sa[8][4];
#pragma unroll
        for (int jt = 0; jt < 8; jt++) {
            sa[jt][0] = sa[jt][1] = sa[jt][2] = sa[jt][3] = 0.f;
            uint32_t kf[4];
            uint32_t addr = ks_base + (uint32_t)((jt * 8 + (lane & 7)) * (ROWP * 2))
                          + (uint32_t)((lane >> 3) * 16);
            ldmx4(kf, addr);
            mma16816(sa[jt], qf[0], qf[1], qf[2], qf[3], kf[0], kf[1]);
            mma16816(sa[jt], qf[4], qf[5], qf[6], qf[7], kf[2], kf[3]);
        }

        // ---- bias + exp + pack to fp16 (PV A-fragments)
        uint32_t ph[8][2];
        int jm = (t + c2) % 7;
#pragma unroll
        for (int jt = 0; jt < 8; jt++) {
            int jm1 = jm + 1; if (jm1 == 7) jm1 = 0;
            float p0 = __expf(sa[jt][0] + b7s[qa7 + jm]);
            float p1 = __expf(sa[jt][1] + b7s[qa7 + jm1]);
            float p2 = __expf(sa[jt][2] + b7s[qb7 + jm]);
            float p3 = __expf(sa[jt][3] + b7s[qb7 + jm1]);
            lA += p0 + p1;
            lB += p2 + p3;
            __half2 hA = __floats2half2_rn(p0, p1);
            __half2 hB = __floats2half2_rn(p2, p3);
            ph[jt][0] = *reinterpret_cast<uint32_t*>(&hA);
            ph[jt][1] = *reinterpret_cast<uint32_t*>(&hB);
            jm = jm1;   // next j-tile: +8 columns == +1 mod 7
        }

        // ---- O += P @ V : 4 k-steps x 4 n-tiles
#pragma unroll
        for (int kt = 0; kt < 4; kt++) {
#pragma unroll
            for (int ntp = 0; ntp < 2; ntp++) {
                uint32_t vf[4];
                uint32_t row = (uint32_t)(kt * 16 + ((lane >> 3) & 1) * 8 + (lane & 7));
                uint32_t col = (uint32_t)(ntp * 16 + (lane >> 4) * 8);
                uint32_t addr = vs_base + row * (ROWP * 2) + col * 2;
                ldmx4t(vf, addr);
                mma16816(oacc[ntp * 2 + 0],
                         ph[kt * 2][0], ph[kt * 2][1],
                         ph[kt * 2 + 1][0], ph[kt * 2 + 1][1],
                         vf[0], vf[1]);
                mma16816(oacc[ntp * 2 + 1],
                         ph[kt * 2][0], ph[kt * 2][1],
                         ph[kt * 2 + 1][0], ph[kt * 2 + 1][1],
                         vf[2], vf[3]);
            }
        }
    }

    // ---- reduce l over the quad (lanes sharing a row)
    lA += __shfl_xor_sync(0xffffffffu, lA, 1);
    lA += __shfl_xor_sync(0xffffffffu, lA, 2);
    lB += __shfl_xor_sync(0xffffffffu, lB, 1);
    lB += __shfl_xor_sync(0xffffffffu, lB, 2);
    const float invA = 1.f / lA;
    const float invB = 1.f / lB;

    float* opA = g_att + (base + qrowA) * HD_;
    float* opB = g_att + (base + qrowB) * HD_;
#pragma unroll
    for (int nt = 0; nt < 4; nt++) {
        float2 va = make_float2(oacc[nt][0] * invA, oacc[nt][1] * invA);
        float2 vb = make_float2(oacc[nt][2] * invB, oacc[nt][3] * invB);
        *(float2*)&opA[nt * 8 + c2] = va;
        *(float2*)&opB[nt * 8 + c2] = vb;
    }
}

// ---------------------------------------------------------------------------
// Kernel 3: output projection (fp32), gathers from g_att
// ---------------------------------------------------------------------------
__global__ __launch_bounds__(256) void proj_gemm_kernel(
    const float* __restrict__ w, const float* __restrict__ bias,
    float* __restrict__ out)
{
    __shared__ float As[BM][BK + 1];
    __shared__ float Bs[BN][BK + 1];

    const int m0 = blockIdx.y * BM;
    const int n0 = blockIdx.x * BN;
    const int tid = threadIdx.x;
    const int tr = tid >> 4;
    const int tc = tid & 15;

    float acc[4][4];
#pragma unroll
    for (int i = 0; i < 4; i++)
#pragma unroll
        for (int j = 0; j < 4; j++) acc[i][j] = 0.f;

    const int lrow = tid >> 2;
    const int lc4  = (tid & 3) * 4;

    for (int k0 = 0; k0 < C_; k0 += BK) {
        const int m = m0 + lrow;
        const int bb = m >> 11;
        const int n  = m & (N_ - 1);
        const int c  = k0 + lc4;
        const int h  = c >> 5;
        const int d  = c & 31;
        float4 a = *(const float4*)&g_att[(((bb * H_ + h) * N_) + n) * HD_ + d];
        As[lrow][lc4 + 0] = a.x; As[lrow][lc4 + 1] = a.y;
        As[lrow][lc4 + 2] = a.z; As[lrow][lc4 + 3] = a.w;
        float4 b = *(const float4*)&w[(n0 + lrow) * C_ + k0 + lc4];
        Bs[lrow][lc4 + 0] = b.x; Bs[lrow][lc4 + 1] = b.y;
        Bs[lrow][lc4 + 2] = b.z; Bs[lrow][lc4 + 3] = b.w;
        __syncthreads();

#pragma unroll
        for (int kk = 0; kk < BK; kk++) {
            float ra[4], rb[4];
#pragma unroll
            for (int i = 0; i < 4; i++) ra[i] = As[tr * 4 + i][kk];
#pragma unroll
            for (int j = 0; j < 4; j++) rb[j] = Bs[tc * 4 + j][kk];
#pragma unroll
            for (int i = 0; i < 4; i++)
#pragma unroll
                for (int j = 0; j < 4; j++) acc[i][j] += ra[i] * rb[j];
        }
        __syncthreads();
    }

#pragma unroll
    for (int i = 0; i < 4; i++) {
        const int m = m0 + tr * 4 + i;
#pragma unroll
        for (int j = 0; j < 4; j++) {
            const int o = n0 + tc * 4 + j;
            out[m * C_ + o] = acc[i][j] + bias[o];
        }
    }
}

// ---------------------------------------------------------------------------
// Launch
// ---------------------------------------------------------------------------
extern "C" void kernel_launch(void* const* d_in, const int* in_sizes, int n_in,
                              void* d_out, int out_size)
{
    const float* x      = (const float*)d_in[0];
    const float* qkv_w  = (const float*)d_in[1];
    const float* qkv_b  = (const float*)d_in[2];
    const float* proj_w = (const float*)d_in[3];
    const float* proj_b = (const float*)d_in[4];
    const float* btab   = (const float*)d_in[5];
    float* out = (float*)d_out;

    (void)in_sizes; (void)n_in; (void)out_size;

    dim3 g1(QKV_OUT / BN, M_ / BM);        // (12, 128)
    qkv_gemm_kernel<<<g1, 256>>>(x, qkv_w, qkv_b);

    dim3 g2(N_ / 64, B_ * H_);             // (32, 32)
    attn_mma_kernel<<<g2, 128>>>(btab);

    dim3 g3(C_ / BN, M_ / BM);             // (4, 128)
    proj_gemm_kernel<<<g3, 256>>>(proj_w, proj_b, out);
}

// round 4
// speedup vs baseline: 3.9346x; 1.1615x over previous
#include <cuda_runtime.h>
#include <cuda_fp16.h>
#include <cstdint>

// ---------------------------------------------------------------------------
// Problem constants
// ---------------------------------------------------------------------------
#define B_   4
#define N_   2048
#define C_   256
#define H_   8
#define HD_  32
#define M_   (B_ * N_)          // 8192
#define QKV_OUT (3 * C_)        // 768
#define SCALE 0.17677669529663687f  // 1/sqrt(32)
#define ELEMS (B_ * H_ * N_ * HD_)  // 2,097,152

__device__ __half g_qh[ELEMS];
__device__ __half g_kh[ELEMS];
__device__ __half g_vh[ELEMS];
__device__ __half g_atth[ELEMS];

// ---------------------------------------------------------------------------
// helpers
// ---------------------------------------------------------------------------
__device__ __forceinline__ uint32_t smem_u32(const void* p) {
    uint32_t a;
    asm("{ .reg .u64 t; cvta.to.shared.u64 t, %1; cvt.u32.u64 %0, t; }"
        : "=r"(a) : "l"(p));
    return a;
}
__device__ __forceinline__ void ldmx4(uint32_t* r, uint32_t addr) {
    asm volatile("ldmatrix.sync.aligned.m8n8.x4.shared.b16 {%0,%1,%2,%3}, [%4];"
        : "=r"(r[0]), "=r"(r[1]), "=r"(r[2]), "=r"(r[3]) : "r"(addr));
}
__device__ __forceinline__ void ldmx4t(uint32_t* r, uint32_t addr) {
    asm volatile("ldmatrix.sync.aligned.m8n8.x4.trans.shared.b16 {%0,%1,%2,%3}, [%4];"
        : "=r"(r[0]), "=r"(r[1]), "=r"(r[2]), "=r"(r[3]) : "r"(addr));
}
__device__ __forceinline__ void mma16816(float* d,
    uint32_t a0, uint32_t a1, uint32_t a2, uint32_t a3,
    uint32_t b0, uint32_t b1) {
    asm volatile("mma.sync.aligned.m16n8k16.row.col.f32.f16.f16.f32 "
        "{%0,%1,%2,%3}, {%4,%5,%6,%7}, {%8,%9}, {%0,%1,%2,%3};"
        : "+f"(d[0]), "+f"(d[1]), "+f"(d[2]), "+f"(d[3])
        : "r"(a0), "r"(a1), "r"(a2), "r"(a3), "r"(b0), "r"(b1));
}

#define ROWP 40   // halfs per padded smem row (80 bytes) — conflict-free ldmatrix

// ---------------------------------------------------------------------------
// Kernel 1: QKV GEMM via mma.sync.
//   CTA 256 thr = 8 warps (4 m x 2 n). Tile BM=128, BN=64, BK=32. K=256.
//   Epilogue: +bias, q scaled, scatter fp16 into g_qh/g_kh/g_vh (B,H,N,hd).
// ---------------------------------------------------------------------------
__global__ __launch_bounds__(256) void qkv_mma_kernel(
    const float* __restrict__ x, const float* __restrict__ w,
    const float* __restrict__ bias)
{
    __shared__ __half Ah[128][ROWP];
    __shared__ __half Bh[64][ROWP];

    const int tid  = threadIdx.x;
    const int lane = tid & 31;
    const int warp = tid >> 5;
    const int wm   = warp & 3;         // 0..3  (32 rows each)
    const int wn   = warp >> 2;        // 0..1  (32 cols each)
    const int m0   = blockIdx.y * 128;
    const int n0   = blockIdx.x * 64;

    const uint32_t a_base = smem_u32(&Ah[0][0]);
    const uint32_t b_base = smem_u32(&Bh[0][0]);

    float acc[2][4][4];   // [mt][nt][frag]
#pragma unroll
    for (int mt = 0; mt < 2; mt++)
#pragma unroll
        for (int nt = 0; nt < 4; nt++)
#pragma unroll
            for (int i = 0; i < 4; i++) acc[mt][nt][i] = 0.f;

    // staging: A 128 rows x 32 cols fp32 -> 2 thr/row, 4 float4 each
    const int arow = tid >> 1;
    const int ac0  = (tid & 1) * 16;   // half-col offset
    // B 64 rows x 32 cols -> 4 thr/row, 2 float4 each
    const int brow = tid >> 2;
    const int bc0  = (tid & 3) * 8;

    for (int k0 = 0; k0 < C_; k0 += 32) {
        __syncthreads();
        {
            const float4* xp = (const float4*)&x[(m0 + arow) * C_ + k0 + ac0];
#pragma unroll
            for (int i = 0; i < 4; i++) {
                float4 v = xp[i];
                __half2 h0 = __floats2half2_rn(v.x, v.y);
                __half2 h1 = __floats2half2_rn(v.z, v.w);
                *(__half2*)&Ah[arow][ac0 + i * 4 + 0] = h0;
                *(__half2*)&Ah[arow][ac0 + i * 4 + 2] = h1;
            }
            const float4* wp = (const float4*)&w[(n0 + brow) * C_ + k0 + bc0];
#pragma unroll
            for (int i = 0; i < 2; i++) {
                float4 v = wp[i];
                __half2 h0 = __floats2half2_rn(v.x, v.y);
                __half2 h1 = __floats2half2_rn(v.z, v.w);
                *(__half2*)&Bh[brow][bc0 + i * 4 + 0] = h0;
                *(__half2*)&Bh[brow][bc0 + i * 4 + 2] = h1;
            }
        }
        __syncthreads();

        // B fragments: 4 n8 tiles, each x4 covers k=0..31
        uint32_t bf[4][4];
#pragma unroll
        for (int nt = 0; nt < 4; nt++) {
            uint32_t addr = b_base
                + (uint32_t)((wn * 32 + nt * 8 + (lane & 7)) * (ROWP * 2))
                + (uint32_t)((lane >> 3) * 16);
            ldmx4(bf[nt], addr);
        }
#pragma unroll
        for (int kk = 0; kk < 2; kk++) {
            uint32_t af[2][4];
#pragma unroll
            for (int mt = 0; mt < 2; mt++) {
                uint32_t addr = a_base
                    + (uint32_t)((wm * 32 + mt * 16 + (lane & 15)) * (ROWP * 2))
                    + (uint32_t)((lane >> 4) * 16 + kk * 32);
                ldmx4(af[mt], addr);
            }
#pragma unroll
            for (int mt = 0; mt < 2; mt++)
#pragma unroll
                for (int nt = 0; nt < 4; nt++)
                    mma16816(acc[mt][nt],
                             af[mt][0], af[mt][1], af[mt][2], af[mt][3],
                             bf[nt][kk * 2], bf[nt][kk * 2 + 1]);
        }
    }

    // epilogue: scatter
    const int rA = lane >> 2;
    const int c2 = (lane & 3) * 2;
#pragma unroll
    for (int mt = 0; mt < 2; mt++) {
#pragma unroll
        for (int half8 = 0; half8 < 2; half8++) {
            const int m = m0 + wm * 32 + mt * 16 + half8 * 8 + rA;
            const int bb = m >> 11;
            const int n  = m & (N_ - 1);
#pragma unroll
            for (int nt = 0; nt < 4; nt++) {
                const int o = n0 + wn * 32 + nt * 8 + c2;
                float v0 = acc[mt][nt][half8 * 2 + 0] + bias[o];
                float v1 = acc[mt][nt][half8 * 2 + 1] + bias[o + 1];
                const int which = o >> 8;
                const int h = (o >> 5) & 7;
                const int d = o & 31;
                const int idx = (((bb * H_ + h) * N_) + n) * HD_ + d;
                if (which == 0) { v0 *= SCALE; v1 *= SCALE; }
                __half2 hv = __floats2half2_rn(v0, v1);
                if (which == 0)      *(__half2*)&g_qh[idx] = hv;
                else if (which == 1) *(__half2*)&g_kh[idx] = hv;
                else                 *(__half2*)&g_vh[idx] = hv;
            }
        }
    }
}

// ---------------------------------------------------------------------------
// Kernel 2: mma.sync fp16 flash attention (as round 3, fp16 output).
// ---------------------------------------------------------------------------
#define KT 64

__global__ __launch_bounds__(128) void attn_mma_kernel(const float* __restrict__ bt)
{
    __shared__ __half Ks[KT][ROWP];
    __shared__ __half Vs[KT][ROWP];
    __shared__ float b7s[49];

    const int tid  = threadIdx.x;
    const int lane = tid & 31;
    const int warp = tid >> 5;
    const int bh = blockIdx.y;
    const int q0 = blockIdx.x * 64;
    const long base = (long)bh * N_;

    if (tid < 49) b7s[tid] = bt[(tid / 7) - (tid % 7) + 6];

    const uint32_t ks_base = smem_u32(&Ks[0][0]);
    const uint32_t vs_base = smem_u32(&Vs[0][0]);

    const int r  = lane >> 2;
    const int cq = lane & 3;
    const int c2 = cq * 2;
    const int qrowA = q0 + warp * 16 + r;
    const int qrowB = qrowA + 8;

    uint32_t qf[8];
    {
        const uint32_t* qpA = (const uint32_t*)(g_qh + (base + qrowA) * HD_);
        const uint32_t* qpB = (const uint32_t*)(g_qh + (base + qrowB) * HD_);
        qf[0] = qpA[cq];      qf[1] = qpB[cq];
        qf[2] = qpA[cq + 4];  qf[3] = qpB[cq + 4];
        qf[4] = qpA[cq + 8];  qf[5] = qpB[cq + 8];
        qf[6] = qpA[cq + 12]; qf[7] = qpB[cq + 12];
    }

    const int qa7 = (qrowA % 7) * 7;
    const int qb7 = (qrowB % 7) * 7;

    float oacc[4][4];
#pragma unroll
    for (int n = 0; n < 4; n++)
#pragma unroll
        for (int i = 0; i < 4; i++) oacc[n][i] = 0.f;
    float lA = 0.f, lB = 0.f;

    const int sj = tid >> 1;
    const int sh = tid & 1;

    for (int t = 0; t < N_; t += KT) {
        __syncthreads();
        {
            const uint4* kp = (const uint4*)(g_kh + (base + t + sj) * HD_);
            const uint4* vp = (const uint4*)(g_vh + (base + t + sj) * HD_);
            *(uint4*)&Ks[sj][sh * 16 + 0] = kp[sh * 2 + 0];
            *(uint4*)&Ks[sj][sh * 16 + 8] = kp[sh * 2 + 1];
            *(uint4*)&Vs[sj][sh * 16 + 0] = vp[sh * 2 + 0];
            *(uint4*)&Vs[sj][sh * 16 + 8] = vp[sh * 2 + 1];
        }
        __syncthreads();

        float sa[8][4];
#pragma unroll
        for (int jt = 0; jt < 8; jt++) {
            sa[jt][0] = sa[jt][1] = sa[jt][2] = sa[jt][3] = 0.f;
            uint32_t kf[4];
            uint32_t addr = ks_base + (uint32_t)((jt * 8 + (lane & 7)) * (ROWP * 2))
                          + (uint32_t)((lane >> 3) * 16);
            ldmx4(kf, addr);
            mma16816(sa[jt], qf[0], qf[1], qf[2], qf[3], kf[0], kf[1]);
            mma16816(sa[jt], qf[4], qf[5], qf[6], qf[7], kf[2], kf[3]);
        }

        uint32_t ph[8][2];
        int jm = (t + c2) % 7;
#pragma unroll
        for (int jt = 0; jt < 8; jt++) {
            int jm1 = jm + 1; if (jm1 == 7) jm1 = 0;
            float p0 = __expf(sa[jt][0] + b7s[qa7 + jm]);
            float p1 = __expf(sa[jt][1] + b7s[qa7 + jm1]);
            float p2 = __expf(sa[jt][2] + b7s[qb7 + jm]);
            float p3 = __expf(sa[jt][3] + b7s[qb7 + jm1]);
            lA += p0 + p1;
            lB += p2 + p3;
            __half2 hA = __floats2half2_rn(p0, p1);
            __half2 hB = __floats2half2_rn(p2, p3);
            ph[jt][0] = *reinterpret_cast<uint32_t*>(&hA);
            ph[jt][1] = *reinterpret_cast<uint32_t*>(&hB);
            jm = jm1;
        }

#pragma unroll
        for (int kt = 0; kt < 4; kt++) {
#pragma unroll
            for (int ntp = 0; ntp < 2; ntp++) {
                uint32_t vf[4];
                uint32_t row = (uint32_t)(kt * 16 + ((lane >> 3) & 1) * 8 + (lane & 7));
                uint32_t col = (uint32_t)(ntp * 16 + (lane >> 4) * 8);
                uint32_t addr = vs_base + row * (ROWP * 2) + col * 2;
                ldmx4t(vf, addr);
                mma16816(oacc[ntp * 2 + 0],
                         ph[kt * 2][0], ph[kt * 2][1],
                         ph[kt * 2 + 1][0], ph[kt * 2 + 1][1],
                         vf[0], vf[1]);
                mma16816(oacc[ntp * 2 + 1],
                         ph[kt * 2][0], ph[kt * 2][1],
                         ph[kt * 2 + 1][0], ph[kt * 2 + 1][1],
                         vf[2], vf[3]);
            }
        }
    }

    lA += __shfl_xor_sync(0xffffffffu, lA, 1);
    lA += __shfl_xor_sync(0xffffffffu, lA, 2);
    lB += __shfl_xor_sync(0xffffffffu, lB, 1);
    lB += __shfl_xor_sync(0xffffffffu, lB, 2);
    const float invA = 1.f / lA;
    const float invB = 1.f / lB;

    __half* opA = g_atth + (base + qrowA) * HD_;
    __half* opB = g_atth + (base + qrowB) * HD_;
#pragma unroll
    for (int nt = 0; nt < 4; nt++) {
        __half2 va = __floats2half2_rn(oacc[nt][0] * invA, oacc[nt][1] * invA);
        __half2 vb = __floats2half2_rn(oacc[nt][2] * invB, oacc[nt][3] * invB);
        *(__half2*)&opA[nt * 8 + c2] = va;
        *(__half2*)&opB[nt * 8 + c2] = vb;
    }
}

// ---------------------------------------------------------------------------
// Kernel 3: proj GEMM via mma.sync. A = g_atth (fp16 gather), B = proj_w.
//   Same tiling as kernel 1. Epilogue: +bias, fp32 out.
// ---------------------------------------------------------------------------
__global__ __launch_bounds__(256) void proj_mma_kernel(
    const float* __restrict__ w, const float* __restrict__ bias,
    float* __restrict__ out)
{
    __shared__ __half Ah[128][ROWP];
    __shared__ __half Bh[64][ROWP];

    const int tid  = threadIdx.x;
    const int lane = tid & 31;
    const int warp = tid >> 5;
    const int wm   = warp & 3;
    const int wn   = warp >> 2;
    const int m0   = blockIdx.y * 128;
    const int n0   = blockIdx.x * 64;

    const uint32_t a_base = smem_u32(&Ah[0][0]);
    const uint32_t b_base = smem_u32(&Bh[0][0]);

    float acc[2][4][4];
#pragma unroll
    for (int mt = 0; mt < 2; mt++)
#pragma unroll
        for (int nt = 0; nt < 4; nt++)
#pragma unroll
            for (int i = 0; i < 4; i++) acc[mt][nt][i] = 0.f;

    const int arow = tid >> 1;         // 2 thr/row, 16 halfs (32B) each
    const int ah0  = (tid & 1) * 16;
    const int brow = tid >> 2;
    const int bc0  = (tid & 3) * 8;

    for (int k0 = 0; k0 < C_; k0 += 32) {
        __syncthreads();
        {
            const int m = m0 + arow;
            const int bb = m >> 11;
            const int n  = m & (N_ - 1);
            const int h  = k0 >> 5;    // BK=32 chunk == one head
            const uint4* ap = (const uint4*)(g_atth
                + (((long)(bb * H_ + h) * N_ + n) * HD_) + ah0);
            *(uint4*)&Ah[arow][ah0 + 0] = ap[0];
            *(uint4*)&Ah[arow][ah0 + 8] = ap[1];

            const float4* wp = (const float4*)&w[(n0 + brow) * C_ + k0 + bc0];
#pragma unroll
            for (int i = 0; i < 2; i++) {
                float4 v = wp[i];
                __half2 h0 = __floats2half2_rn(v.x, v.y);
                __half2 h1 = __floats2half2_rn(v.z, v.w);
                *(__half2*)&Bh[brow][bc0 + i * 4 + 0] = h0;
                *(__half2*)&Bh[brow][bc0 + i * 4 + 2] = h1;
            }
        }
        __syncthreads();

        uint32_t bf[4][4];
#pragma unroll
        for (int nt = 0; nt < 4; nt++) {
            uint32_t addr = b_base
                + (uint32_t)((wn * 32 + nt * 8 + (lane & 7)) * (ROWP * 2))
                + (uint32_t)((lane >> 3) * 16);
            ldmx4(bf[nt], addr);
        }
#pragma unroll
        for (int kk = 0; kk < 2; kk++) {
            uint32_t af[2][4];
#pragma unroll
            for (int mt = 0; mt < 2; mt++) {
                uint32_t addr = a_base
                    + (uint32_t)((wm * 32 + mt * 16 + (lane & 15)) * (ROWP * 2))
                    + (uint32_t)((lane >> 4) * 16 + kk * 32);
                ldmx4(af[mt], addr);
            }
#pragma unroll
            for (int mt = 0; mt < 2; mt++)
#pragma unroll
                for (int nt = 0; nt < 4; nt++)
                    mma16816(acc[mt][nt],
                             af[mt][0], af[mt][1], af[mt][2], af[mt][3],
                             bf[nt][kk * 2], bf[nt][kk * 2 + 1]);
        }
    }

    const int rA = lane >> 2;
    const int c2 = (lane & 3) * 2;
#pragma unroll
    for (int mt = 0; mt < 2; mt++) {
#pragma unroll
        for (int half8 = 0; half8 < 2; half8++) {
            const int m = m0 + wm * 32 + mt * 16 + half8 * 8 + rA;
#pragma unroll
            for (int nt = 0; nt < 4; nt++) {
                const int o = n0 + wn * 32 + nt * 8 + c2;
                float2 v;
                v.x = acc[mt][nt][half8 * 2 + 0] + bias[o];
                v.y = acc[mt][nt][half8 * 2 + 1] + bias[o + 1];
                *(float2*)&out[m * C_ + o] = v;
            }
        }
    }
}

// ---------------------------------------------------------------------------
// Launch
// ---------------------------------------------------------------------------
extern "C" void kernel_launch(void* const* d_in, const int* in_sizes, int n_in,
                              void* d_out, int out_size)
{
    const float* x      = (const float*)d_in[0];
    const float* qkv_w  = (const float*)d_in[1];
    const float* qkv_b  = (const float*)d_in[2];
    const float* proj_w = (const float*)d_in[3];
    const float* proj_b = (const float*)d_in[4];
    const float* btab   = (const float*)d_in[5];
    float* out = (float*)d_out;

    (void)in_sizes; (void)n_in; (void)out_size;

    dim3 g1(QKV_OUT / 64, M_ / 128);       // (12, 64)
    qkv_mma_kernel<<<g1, 256>>>(x, qkv_w, qkv_b);

    dim3 g2(N_ / 64, B_ * H_);             // (32, 32)
    attn_mma_kernel<<<g2, 128>>>(btab);

    dim3 g3(C_ / 64, M_ / 128);            // (4, 64)
    proj_mma_kernel<<<g3, 256>>>(proj_w, proj_b, out);
}

// round 5
// speedup vs baseline: 6.1871x; 1.5725x over previous
#include <cuda_runtime.h>
#include <cuda_fp16.h>
#include <cstdint>

// ---------------------------------------------------------------------------
// Problem constants
// ---------------------------------------------------------------------------
#define B_   4
#define N_   2048
#define C_   256
#define H_   8
#define HD_  32
#define M_   (B_ * N_)          // 8192
#define QKV_OUT (3 * C_)        // 768
#define SCALE 0.17677669529663687f  // 1/sqrt(32)
#define ELEMS (B_ * H_ * N_ * HD_)  // 2,097,152

__device__ __half g_qh[ELEMS];
__device__ __half g_kh[ELEMS];
__device__ __half g_vh[ELEMS];
__device__ __half g_atth[ELEMS];

// ---------------------------------------------------------------------------
// helpers
// ---------------------------------------------------------------------------
__device__ __forceinline__ uint32_t smem_u32(const void* p) {
    uint32_t a;
    asm("{ .reg .u64 t; cvta.to.shared.u64 t, %1; cvt.u32.u64 %0, t; }"
        : "=r"(a) : "l"(p));
    return a;
}
__device__ __forceinline__ void ldmx4(uint32_t* r, uint32_t addr) {
    asm volatile("ldmatrix.sync.aligned.m8n8.x4.shared.b16 {%0,%1,%2,%3}, [%4];"
        : "=r"(r[0]), "=r"(r[1]), "=r"(r[2]), "=r"(r[3]) : "r"(addr));
}
__device__ __forceinline__ void ldmx4t(uint32_t* r, uint32_t addr) {
    asm volatile("ldmatrix.sync.aligned.m8n8.x4.trans.shared.b16 {%0,%1,%2,%3}, [%4];"
        : "=r"(r[0]), "=r"(r[1]), "=r"(r[2]), "=r"(r[3]) : "r"(addr));
}
__device__ __forceinline__ void mma16816(float* d,
    uint32_t a0, uint32_t a1, uint32_t a2, uint32_t a3,
    uint32_t b0, uint32_t b1) {
    asm volatile("mma.sync.aligned.m16n8k16.row.col.f32.f16.f16.f32 "
        "{%0,%1,%2,%3}, {%4,%5,%6,%7}, {%8,%9}, {%0,%1,%2,%3};"
        : "+f"(d[0]), "+f"(d[1]), "+f"(d[2]), "+f"(d[3])
        : "r"(a0), "r"(a1), "r"(a2), "r"(a3), "r"(b0), "r"(b1));
}

#define ROWP 40   // halfs per padded smem row (80 bytes) — conflict-free ldmatrix

// ---------------------------------------------------------------------------
// Kernel 1: QKV GEMM via mma.sync, 2-stage double-buffered.
//   CTA 256 thr = 8 warps (4 m x 2 n). Tile BM=128, BN=64, BK=32. K=256.
// ---------------------------------------------------------------------------
__global__ __launch_bounds__(256) void qkv_mma_kernel(
    const float* __restrict__ x, const float* __restrict__ w,
    const float* __restrict__ bias)
{
    __shared__ __half Ah[2][128][ROWP];
    __shared__ __half Bh[2][64][ROWP];

    const int tid  = threadIdx.x;
    const int lane = tid & 31;
    const int warp = tid >> 5;
    const int wm   = warp & 3;
    const int wn   = warp >> 2;
    const int m0   = blockIdx.y * 128;
    const int n0   = blockIdx.x * 64;

    const uint32_t a_base0 = smem_u32(&Ah[0][0][0]);
    const uint32_t b_base0 = smem_u32(&Bh[0][0][0]);
    const uint32_t a_stride = 128 * ROWP * 2;
    const uint32_t b_stride = 64 * ROWP * 2;

    float acc[2][4][4];
#pragma unroll
    for (int mt = 0; mt < 2; mt++)
#pragma unroll
        for (int nt = 0; nt < 4; nt++)
#pragma unroll
            for (int i = 0; i < 4; i++) acc[mt][nt][i] = 0.f;

    const int arow = tid >> 1;
    const int ac0  = (tid & 1) * 16;
    const int brow = tid >> 2;
    const int bc0  = (tid & 3) * 8;

    float4 ar[4], br[2];
    // prologue: load + stage k0 = 0
    {
        const float4* xp = (const float4*)&x[(m0 + arow) * C_ + ac0];
#pragma unroll
        for (int i = 0; i < 4; i++) ar[i] = xp[i];
        const float4* wp = (const float4*)&w[(n0 + brow) * C_ + bc0];
#pragma unroll
        for (int i = 0; i < 2; i++) br[i] = wp[i];
#pragma unroll
        for (int i = 0; i < 4; i++) {
            *(__half2*)&Ah[0][arow][ac0 + i * 4 + 0] = __floats2half2_rn(ar[i].x, ar[i].y);
            *(__half2*)&Ah[0][arow][ac0 + i * 4 + 2] = __floats2half2_rn(ar[i].z, ar[i].w);
        }
#pragma unroll
        for (int i = 0; i < 2; i++) {
            *(__half2*)&Bh[0][brow][bc0 + i * 4 + 0] = __floats2half2_rn(br[i].x, br[i].y);
            *(__half2*)&Bh[0][brow][bc0 + i * 4 + 2] = __floats2half2_rn(br[i].z, br[i].w);
        }
    }
    __syncthreads();

    int buf = 0;
#pragma unroll
    for (int it = 0; it < 8; it++) {
        // prefetch next K-step
        if (it < 7) {
            const int k0n = (it + 1) * 32;
            const float4* xp = (const float4*)&x[(m0 + arow) * C_ + k0n + ac0];
#pragma unroll
            for (int i = 0; i < 4; i++) ar[i] = xp[i];
            const float4* wp = (const float4*)&w[(n0 + brow) * C_ + k0n + bc0];
#pragma unroll
            for (int i = 0; i < 2; i++) br[i] = wp[i];
        }

        // compute current buffer
        const uint32_t a_base = a_base0 + (uint32_t)buf * a_stride;
        const uint32_t b_base = b_base0 + (uint32_t)buf * b_stride;
        uint32_t bf[4][4];
#pragma unroll
        for (int nt = 0; nt < 4; nt++) {
            uint32_t addr = b_base
                + (uint32_t)((wn * 32 + nt * 8 + (lane & 7)) * (ROWP * 2))
                + (uint32_t)((lane >> 3) * 16);
            ldmx4(bf[nt], addr);
        }
#pragma unroll
        for (int kk = 0; kk < 2; kk++) {
            uint32_t af[2][4];
#pragma unroll
            for (int mt = 0; mt < 2; mt++) {
                uint32_t addr = a_base
                    + (uint32_t)((wm * 32 + mt * 16 + (lane & 15)) * (ROWP * 2))
                    + (uint32_t)((lane >> 4) * 16 + kk * 32);
                ldmx4(af[mt], addr);
            }
#pragma unroll
            for (int mt = 0; mt < 2; mt++)
#pragma unroll
                for (int nt = 0; nt < 4; nt++)
                    mma16816(acc[mt][nt],
                             af[mt][0], af[mt][1], af[mt][2], af[mt][3],
                             bf[nt][kk * 2], bf[nt][kk * 2 + 1]);
        }

        if (it < 7) {
            const int nb = buf ^ 1;
#pragma unroll
            for (int i = 0; i < 4; i++) {
                *(__half2*)&Ah[nb][arow][ac0 + i * 4 + 0] = __floats2half2_rn(ar[i].x, ar[i].y);
                *(__half2*)&Ah[nb][arow][ac0 + i * 4 + 2] = __floats2half2_rn(ar[i].z, ar[i].w);
            }
#pragma unroll
            for (int i = 0; i < 2; i++) {
                *(__half2*)&Bh[nb][brow][bc0 + i * 4 + 0] = __floats2half2_rn(br[i].x, br[i].y);
                *(__half2*)&Bh[nb][brow][bc0 + i * 4 + 2] = __floats2half2_rn(br[i].z, br[i].w);
            }
            __syncthreads();
            buf = nb;
        }
    }

    // epilogue: scatter fp16 q/k/v
    const int rA = lane >> 2;
    const int c2 = (lane & 3) * 2;
#pragma unroll
    for (int mt = 0; mt < 2; mt++) {
#pragma unroll
        for (int half8 = 0; half8 < 2; half8++) {
            const int m = m0 + wm * 32 + mt * 16 + half8 * 8 + rA;
            const int bb = m >> 11;
            const int n  = m & (N_ - 1);
#pragma unroll
            for (int nt = 0; nt < 4; nt++) {
                const int o = n0 + wn * 32 + nt * 8 + c2;
                float v0 = acc[mt][nt][half8 * 2 + 0] + bias[o];
                float v1 = acc[mt][nt][half8 * 2 + 1] + bias[o + 1];
                const int which = o >> 8;
                const int h = (o >> 5) & 7;
                const int d = o & 31;
                const int idx = (((bb * H_ + h) * N_) + n) * HD_ + d;
                if (which == 0) { v0 *= SCALE; v1 *= SCALE; }
                __half2 hv = __floats2half2_rn(v0, v1);
                if (which == 0)      *(__half2*)&g_qh[idx] = hv;
                else if (which == 1) *(__half2*)&g_kh[idx] = hv;
                else                 *(__half2*)&g_vh[idx] = hv;
            }
        }
    }
}

// ---------------------------------------------------------------------------
// Kernel 2: mma.sync fp16 flash attention, double-buffered KV staging.
// ---------------------------------------------------------------------------
#define KT 64

__global__ __launch_bounds__(128) void attn_mma_kernel(const float* __restrict__ bt)
{
    __shared__ __half Ks[2][KT][ROWP];
    __shared__ __half Vs[2][KT][ROWP];
    __shared__ float b7s[49];

    const int tid  = threadIdx.x;
    const int lane = tid & 31;
    const int warp = tid >> 5;
    const int bh = blockIdx.y;
    const int q0 = blockIdx.x * 64;
    const long base = (long)bh * N_;

    if (tid < 49) b7s[tid] = bt[(tid / 7) - (tid % 7) + 6];

    const uint32_t ks_base0 = smem_u32(&Ks[0][0][0]);
    const uint32_t vs_base0 = smem_u32(&Vs[0][0][0]);
    const uint32_t kv_stride = KT * ROWP * 2;

    const int r  = lane >> 2;
    const int cq = lane & 3;
    const int c2 = cq * 2;
    const int qrowA = q0 + warp * 16 + r;
    const int qrowB = qrowA + 8;

    uint32_t qf[8];
    {
        const uint32_t* qpA = (const uint32_t*)(g_qh + (base + qrowA) * HD_);
        const uint32_t* qpB = (const uint32_t*)(g_qh + (base + qrowB) * HD_);
        qf[0] = qpA[cq];      qf[1] = qpB[cq];
        qf[2] = qpA[cq + 4];  qf[3] = qpB[cq + 4];
        qf[4] = qpA[cq + 8];  qf[5] = qpB[cq + 8];
        qf[6] = qpA[cq + 12]; qf[7] = qpB[cq + 12];
    }

    const int qa7 = (qrowA % 7) * 7;
    const int qb7 = (qrowB % 7) * 7;

    float oacc[4][4];
#pragma unroll
    for (int n = 0; n < 4; n++)
#pragma unroll
        for (int i = 0; i < 4; i++) oacc[n][i] = 0.f;
    float lA = 0.f, lB = 0.f;

    const int sj = tid >> 1;
    const int sh = tid & 1;

    uint4 kr[2], vr[2];
    // prologue: load + stage tile t=0
    {
        const uint4* kp = (const uint4*)(g_kh + (base + sj) * HD_);
        const uint4* vp = (const uint4*)(g_vh + (base + sj) * HD_);
        kr[0] = kp[sh * 2 + 0]; kr[1] = kp[sh * 2 + 1];
        vr[0] = vp[sh * 2 + 0]; vr[1] = vp[sh * 2 + 1];
        *(uint4*)&Ks[0][sj][sh * 16 + 0] = kr[0];
        *(uint4*)&Ks[0][sj][sh * 16 + 8] = kr[1];
        *(uint4*)&Vs[0][sj][sh * 16 + 0] = vr[0];
        *(uint4*)&Vs[0][sj][sh * 16 + 8] = vr[1];
    }
    __syncthreads();

    int buf = 0;
    for (int it = 0; it < N_ / KT; it++) {
        const int t = it * KT;
        // prefetch next tile
        if (it < N_ / KT - 1) {
            const uint4* kp = (const uint4*)(g_kh + (base + t + KT + sj) * HD_);
            const uint4* vp = (const uint4*)(g_vh + (base + t + KT + sj) * HD_);
            kr[0] = kp[sh * 2 + 0]; kr[1] = kp[sh * 2 + 1];
            vr[0] = vp[sh * 2 + 0]; vr[1] = vp[sh * 2 + 1];
        }

        const uint32_t ks_base = ks_base0 + (uint32_t)buf * kv_stride;
        const uint32_t vs_base = vs_base0 + (uint32_t)buf * kv_stride;

        // ---- S = Q @ K^T
        float sa[8][4];
#pragma unroll
        for (int jt = 0; jt < 8; jt++) {
            sa[jt][0] = sa[jt][1] = sa[jt][2] = sa[jt][3] = 0.f;
            uint32_t kf[4];
            uint32_t addr = ks_base + (uint32_t)((jt * 8 + (lane & 7)) * (ROWP * 2))
                          + (uint32_t)((lane >> 3) * 16);
            ldmx4(kf, addr);
            mma16816(sa[jt], qf[0], qf[1], qf[2], qf[3], kf[0], kf[1]);
            mma16816(sa[jt], qf[4], qf[5], qf[6], qf[7], kf[2], kf[3]);
        }

        // ---- bias + exp + pack
        uint32_t ph[8][2];
        int jm = (t + c2) % 7;
#pragma unroll
        for (int jt = 0; jt < 8; jt++) {
            int jm1 = jm + 1; if (jm1 == 7) jm1 = 0;
            float p0 = __expf(sa[jt][0] + b7s[qa7 + jm]);
            float p1 = __expf(sa[jt][1] + b7s[qa7 + jm1]);
            float p2 = __expf(sa[jt][2] + b7s[qb7 + jm]);
            float p3 = __expf(sa[jt][3] + b7s[qb7 + jm1]);
            lA += p0 + p1;
            lB += p2 + p3;
            __half2 hA = __floats2half2_rn(p0, p1);
            __half2 hB = __floats2half2_rn(p2, p3);
            ph[jt][0] = *reinterpret_cast<uint32_t*>(&hA);
            ph[jt][1] = *reinterpret_cast<uint32_t*>(&hB);
            jm = jm1;
        }

        // ---- O += P @ V
#pragma unroll
        for (int kt = 0; kt < 4; kt++) {
#pragma unroll
            for (int ntp = 0; ntp < 2; ntp++) {
                uint32_t vf[4];
                uint32_t row = (uint32_t)(kt * 16 + ((lane >> 3) & 1) * 8 + (lane & 7));
                uint32_t col = (uint32_t)(ntp * 16 + (lane >> 4) * 8);
                uint32_t addr = vs_base + row * (ROWP * 2) + col * 2;
                ldmx4t(vf, addr);
                mma16816(oacc[ntp * 2 + 0],
                         ph[kt * 2][0], ph[kt * 2][1],
                         ph[kt * 2 + 1][0], ph[kt * 2 + 1][1],
                         vf[0], vf[1]);
                mma16816(oacc[ntp * 2 + 1],
                         ph[kt * 2][0], ph[kt * 2][1],
                         ph[kt * 2 + 1][0], ph[kt * 2 + 1][1],
                         vf[2], vf[3]);
            }
        }

        if (it < N_ / KT - 1) {
            const int nb = buf ^ 1;
            *(uint4*)&Ks[nb][sj][sh * 16 + 0] = kr[0];
            *(uint4*)&Ks[nb][sj][sh * 16 + 8] = kr[1];
            *(uint4*)&Vs[nb][sj][sh * 16 + 0] = vr[0];
            *(uint4*)&Vs[nb][sj][sh * 16 + 8] = vr[1];
            __syncthreads();
            buf = nb;
        }
    }

    lA += __shfl_xor_sync(0xffffffffu, lA, 1);
    lA += __shfl_xor_sync(0xffffffffu, lA, 2);
    lB += __shfl_xor_sync(0xffffffffu, lB, 1);
    lB += __shfl_xor_sync(0xffffffffu, lB, 2);
    const float invA = 1.f / lA;
    const float invB = 1.f / lB;

    __half* opA = g_atth + (base + qrowA) * HD_;
    __half* opB = g_atth + (base + qrowB) * HD_;
#pragma unroll
    for (int nt = 0; nt < 4; nt++) {
        __half2 va = __floats2half2_rn(oacc[nt][0] * invA, oacc[nt][1] * invA);
        __half2 vb = __floats2half2_rn(oacc[nt][2] * invB, oacc[nt][3] * invB);
        *(__half2*)&opA[nt * 8 + c2] = va;
        *(__half2*)&opB[nt * 8 + c2] = vb;
    }
}

// ---------------------------------------------------------------------------
// Kernel 3: proj GEMM via mma.sync, double-buffered. A = g_atth fp16 gather.
// ---------------------------------------------------------------------------
__global__ __launch_bounds__(256) void proj_mma_kernel(
    const float* __restrict__ w, const float* __restrict__ bias,
    float* __restrict__ out)
{
    __shared__ __half Ah[2][128][ROWP];
    __shared__ __half Bh[2][64][ROWP];

    const int tid  = threadIdx.x;
    const int lane = tid & 31;
    const int warp = tid >> 5;
    const int wm   = warp & 3;
    const int wn   = warp >> 2;
    const int m0   = blockIdx.y * 128;
    const int n0   = blockIdx.x * 64;

    const uint32_t a_base0 = smem_u32(&Ah[0][0][0]);
    const uint32_t b_base0 = smem_u32(&Bh[0][0][0]);
    const uint32_t a_stride = 128 * ROWP * 2;
    const uint32_t b_stride = 64 * ROWP * 2;

    float acc[2][4][4];
#pragma unroll
    for (int mt = 0; mt < 2; mt++)
#pragma unroll
        for (int nt = 0; nt < 4; nt++)
#pragma unroll
            for (int i = 0; i < 4; i++) acc[mt][nt][i] = 0.f;

    const int arow = tid >> 1;
    const int ah0  = (tid & 1) * 16;
    const int brow = tid >> 2;
    const int bc0  = (tid & 3) * 8;

    const int m  = m0 + arow;
    const int bb = m >> 11;
    const int nn = m & (N_ - 1);

    uint4 apr[2];
    float4 br[2];
    {
        const uint4* ap = (const uint4*)(g_atth + (((long)(bb * H_ + 0) * N_ + nn) * HD_) + ah0);
        apr[0] = ap[0]; apr[1] = ap[1];
        const float4* wp = (const float4*)&w[(n0 + brow) * C_ + bc0];
        br[0] = wp[0]; br[1] = wp[1];
        *(uint4*)&Ah[0][arow][ah0 + 0] = apr[0];
        *(uint4*)&Ah[0][arow][ah0 + 8] = apr[1];
#pragma unroll
        for (int i = 0; i < 2; i++) {
            *(__half2*)&Bh[0][brow][bc0 + i * 4 + 0] = __floats2half2_rn(br[i].x, br[i].y);
            *(__half2*)&Bh[0][brow][bc0 + i * 4 + 2] = __floats2half2_rn(br[i].z, br[i].w);
        }
    }
    __syncthreads();

    int buf = 0;
#pragma unroll
    for (int it = 0; it < 8; it++) {
        if (it < 7) {
            const int k0n = (it + 1) * 32;
            const int h = k0n >> 5;
            const uint4* ap = (const uint4*)(g_atth + (((long)(bb * H_ + h) * N_ + nn) * HD_) + ah0);
            apr[0] = ap[0]; apr[1] = ap[1];
            const float4* wp = (const float4*)&w[(n0 + brow) * C_ + k0n + bc0];
            br[0] = wp[0]; br[1] = wp[1];
        }

        const uint32_t a_base = a_base0 + (uint32_t)buf * a_stride;
        const uint32_t b_base = b_base0 + (uint32_t)buf * b_stride;
        uint32_t bf[4][4];
#pragma unroll
        for (int nt = 0; nt < 4; nt++) {
            uint32_t addr = b_base
                + (uint32_t)((wn * 32 + nt * 8 + (lane & 7)) * (ROWP * 2))
                + (uint32_t)((lane >> 3) * 16);
            ldmx4(bf[nt], addr);
        }
#pragma unroll
        for (int kk = 0; kk < 2; kk++) {
            uint32_t af[2][4];
#pragma unroll
            for (int mt = 0; mt < 2; mt++) {
                uint32_t addr = a_base
                    + (uint32_t)((wm * 32 + mt * 16 + (lane & 15)) * (ROWP * 2))
                    + (uint32_t)((lane >> 4) * 16 + kk * 32);
                ldmx4(af[mt], addr);
            }
#pragma unroll
            for (int mt = 0; mt < 2; mt++)
#pragma unroll
                for (int nt = 0; nt < 4; nt++)
                    mma16816(acc[mt][nt],
                             af[mt][0], af[mt][1], af[mt][2], af[mt][3],
                             bf[nt][kk * 2], bf[nt][kk * 2 + 1]);
        }

        if (it < 7) {
            const int nb = buf ^ 1;
            *(uint4*)&Ah[nb][arow][ah0 + 0] = apr[0];
            *(uint4*)&Ah[nb][arow][ah0 + 8] = apr[1];
#pragma unroll
            for (int i = 0; i < 2; i++) {
                *(__half2*)&Bh[nb][brow][bc0 + i * 4 + 0] = __floats2half2_rn(br[i].x, br[i].y);
                *(__half2*)&Bh[nb][brow][bc0 + i * 4 + 2] = __floats2half2_rn(br[i].z, br[i].w);
            }
            __syncthreads();
            buf = nb;
        }
    }

    const int rA = lane >> 2;
    const int c2 = (lane & 3) * 2;
#pragma unroll
    for (int mt = 0; mt < 2; mt++) {
#pragma unroll
        for (int half8 = 0; half8 < 2; half8++) {
            const int mm = m0 + wm * 32 + mt * 16 + half8 * 8 + rA;
#pragma unroll
            for (int nt = 0; nt < 4; nt++) {
                const int o = n0 + wn * 32 + nt * 8 + c2;
                float2 v;
                v.x = acc[mt][nt][half8 * 2 + 0] + bias[o];
                v.y = acc[mt][nt][half8 * 2 + 1] + bias[o + 1];
                *(float2*)&out[mm * C_ + o] = v;
            }
        }
    }
}

// ---------------------------------------------------------------------------
// Launch
// ---------------------------------------------------------------------------
extern "C" void kernel_launch(void* const* d_in, const int* in_sizes, int n_in,
                              void* d_out, int out_size)
{
    const float* x      = (const float*)d_in[0];
    const float* qkv_w  = (const float*)d_in[1];
    const float* qkv_b  = (const float*)d_in[2];
    const float* proj_w = (const float*)d_in[3];
    const float* proj_b = (const float*)d_in[4];
    const float* btab   = (const float*)d_in[5];
    float* out = (float*)d_out;

    (void)in_sizes; (void)n_in; (void)out_size;

    dim3 g1(QKV_OUT / 64, M_ / 128);       // (12, 64)
    qkv_mma_kernel<<<g1, 256>>>(x, qkv_w, qkv_b);

    dim3 g2(N_ / 64, B_ * H_);             // (32, 32)
    attn_mma_kernel<<<g2, 128>>>(btab);

    dim3 g3(C_ / 64, M_ / 128);            // (4, 64)
    proj_mma_kernel<<<g3, 256>>>(proj_w, proj_b, out);
}

// round 6
// speedup vs baseline: 6.8984x; 1.1150x over previous
#include <cuda_runtime.h>
#include <cuda_fp16.h>
#include <cstdint>

// ---------------------------------------------------------------------------
// Problem constants
// ---------------------------------------------------------------------------
#define B_   4
#define N_   2048
#define C_   256
#define H_   8
#define HD_  32
#define M_   (B_ * N_)          // 8192
#define QKV_OUT (3 * C_)        // 768
#define SCALE 0.17677669529663687f  // 1/sqrt(32)
#define ELEMS (B_ * H_ * N_ * HD_)  // 2,097,152

#define XE (M_ * C_)            // 2,097,152
#define WE (QKV_OUT * C_)       // 196,608
#define PE (C_ * C_)            // 65,536

__device__ __half g_qh[ELEMS];
__device__ __half g_kh[ELEMS];
__device__ __half g_vh[ELEMS];
__device__ __half g_atth[ELEMS];
__device__ __half g_xh[XE];
__device__ __half g_wh[WE];
__device__ __half g_pwh[PE];

// ---------------------------------------------------------------------------
// helpers
// ---------------------------------------------------------------------------
__device__ __forceinline__ uint32_t smem_u32(const void* p) {
    uint32_t a;
    asm("{ .reg .u64 t; cvta.to.shared.u64 t, %1; cvt.u32.u64 %0, t; }"
        : "=r"(a) : "l"(p));
    return a;
}
__device__ __forceinline__ void ldmx4(uint32_t* r, uint32_t addr) {
    asm volatile("ldmatrix.sync.aligned.m8n8.x4.shared.b16 {%0,%1,%2,%3}, [%4];"
        : "=r"(r[0]), "=r"(r[1]), "=r"(r[2]), "=r"(r[3]) : "r"(addr));
}
__device__ __forceinline__ void ldmx4t(uint32_t* r, uint32_t addr) {
    asm volatile("ldmatrix.sync.aligned.m8n8.x4.trans.shared.b16 {%0,%1,%2,%3}, [%4];"
        : "=r"(r[0]), "=r"(r[1]), "=r"(r[2]), "=r"(r[3]) : "r"(addr));
}
__device__ __forceinline__ void mma16816(float* d,
    uint32_t a0, uint32_t a1, uint32_t a2, uint32_t a3,
    uint32_t b0, uint32_t b1) {
    asm volatile("mma.sync.aligned.m16n8k16.row.col.f32.f16.f16.f32 "
        "{%0,%1,%2,%3}, {%4,%5,%6,%7}, {%8,%9}, {%0,%1,%2,%3};"
        : "+f"(d[0]), "+f"(d[1]), "+f"(d[2]), "+f"(d[3])
        : "r"(a0), "r"(a1), "r"(a2), "r"(a3), "r"(b0), "r"(b1));
}
__device__ __forceinline__ void cp16(uint32_t s, const void* g) {
    asm volatile("cp.async.cg.shared.global [%0], [%1], 16;"
        :: "r"(s), "l"(g) : "memory");
}
#define CP_COMMIT() asm volatile("cp.async.commit_group;" ::: "memory")
#define CP_WAIT0()  asm volatile("cp.async.wait_group 0;" ::: "memory")

#define ROWP 40   // halfs per padded smem row (80 bytes) — conflict-free ldmatrix

// ---------------------------------------------------------------------------
// Kernel 0: fp32 -> fp16 pre-convert of x, qkv_w, proj_w
// ---------------------------------------------------------------------------
__global__ __launch_bounds__(256) void conv_kernel(
    const float* __restrict__ x, const float* __restrict__ w,
    const float* __restrict__ pw)
{
    const int i = (blockIdx.x * 256 + threadIdx.x) * 4;
    const float* src; __half* dst; int off;
    if (i < XE)            { src = x;  dst = g_xh;  off = i; }
    else if (i < XE + WE)  { src = w;  dst = g_wh;  off = i - XE; }
    else                   { src = pw; dst = g_pwh; off = i - XE - WE; }
    float4 v = *(const float4*)&src[off];
    *(__half2*)&dst[off + 0] = __floats2half2_rn(v.x, v.y);
    *(__half2*)&dst[off + 2] = __floats2half2_rn(v.z, v.w);
}

// ---------------------------------------------------------------------------
// Kernel 1: QKV GEMM via mma.sync, cp.async double-buffered, fp16 inputs.
//   CTA 256 thr = 8 warps (4 m x 2 n). BM=128, BN=64, BK=32, K=256.
// ---------------------------------------------------------------------------
__global__ __launch_bounds__(256) void qkv_mma_kernel(const float* __restrict__ bias)
{
    __shared__ __align__(16) __half Ah[2][128][ROWP];
    __shared__ __align__(16) __half Bh[2][64][ROWP];

    const int tid  = threadIdx.x;
    const int lane = tid & 31;
    const int warp = tid >> 5;
    const int wm   = warp & 3;
    const int wn   = warp >> 2;
    const int m0   = blockIdx.y * 128;
    const int n0   = blockIdx.x * 64;

    const uint32_t a_base0 = smem_u32(&Ah[0][0][0]);
    const uint32_t b_base0 = smem_u32(&Bh[0][0][0]);
    const uint32_t a_stride = 128 * ROWP * 2;
    const uint32_t b_stride = 64 * ROWP * 2;

    float acc[2][4][4];
#pragma unroll
    for (int mt = 0; mt < 2; mt++)
#pragma unroll
        for (int nt = 0; nt < 4; nt++)
#pragma unroll
            for (int i = 0; i < 4; i++) acc[mt][nt][i] = 0.f;

    // staging: A row=tid>>1, 2x16B; B row=tid>>2, 1x16B
    const int arow = tid >> 1;
    const int ach  = tid & 1;
    const int brow = tid >> 2;
    const int bch  = tid & 3;
    const uint32_t a_so = (uint32_t)arow * 80u + (uint32_t)ach * 32u;
    const uint32_t b_so = (uint32_t)brow * 80u + (uint32_t)bch * 16u;
    const __half* agp = g_xh + (m0 + arow) * C_ + ach * 16;
    const __half* bgp = g_wh + (n0 + brow) * C_ + bch * 8;

#define QKV_STAGE(k0, bufn) do { \
        cp16(a_base0 + (bufn) * a_stride + a_so +  0, agp + (k0));       \
        cp16(a_base0 + (bufn) * a_stride + a_so + 16, agp + (k0) + 8);   \
        cp16(b_base0 + (bufn) * b_stride + b_so,      bgp + (k0));       \
    } while (0)

    QKV_STAGE(0, 0); CP_COMMIT();

    int buf = 0;
#pragma unroll
    for (int it = 0; it < 8; it++) {
        CP_WAIT0();
        __syncthreads();
        if (it < 7) { QKV_STAGE((it + 1) * 32, buf ^ 1); CP_COMMIT(); }

        const uint32_t a_base = a_base0 + (uint32_t)buf * a_stride;
        const uint32_t b_base = b_base0 + (uint32_t)buf * b_stride;
        uint32_t bf[4][4];
#pragma unroll
        for (int nt = 0; nt < 4; nt++) {
            uint32_t addr = b_base
                + (uint32_t)((wn * 32 + nt * 8 + (lane & 7)) * (ROWP * 2))
                + (uint32_t)((lane >> 3) * 16);
            ldmx4(bf[nt], addr);
        }
#pragma unroll
        for (int kk = 0; kk < 2; kk++) {
            uint32_t af[2][4];
#pragma unroll
            for (int mt = 0; mt < 2; mt++) {
                uint32_t addr = a_base
                    + (uint32_t)((wm * 32 + mt * 16 + (lane & 15)) * (ROWP * 2))
                    + (uint32_t)((lane >> 4) * 16 + kk * 32);
                ldmx4(af[mt], addr);
            }
#pragma unroll
            for (int mt = 0; mt < 2; mt++)
#pragma unroll
                for (int nt = 0; nt < 4; nt++)
                    mma16816(acc[mt][nt],
                             af[mt][0], af[mt][1], af[mt][2], af[mt][3],
                             bf[nt][kk * 2], bf[nt][kk * 2 + 1]);
        }
        buf ^= 1;
    }

    // epilogue: scatter fp16 q/k/v
    const int rA = lane >> 2;
    const int c2 = (lane & 3) * 2;
#pragma unroll
    for (int mt = 0; mt < 2; mt++) {
#pragma unroll
        for (int half8 = 0; half8 < 2; half8++) {
            const int m = m0 + wm * 32 + mt * 16 + half8 * 8 + rA;
            const int bb = m >> 11;
            const int n  = m & (N_ - 1);
#pragma unroll
            for (int nt = 0; nt < 4; nt++) {
                const int o = n0 + wn * 32 + nt * 8 + c2;
                float v0 = acc[mt][nt][half8 * 2 + 0] + bias[o];
                float v1 = acc[mt][nt][half8 * 2 + 1] + bias[o + 1];
                const int which = o >> 8;
                const int h = (o >> 5) & 7;
                const int d = o & 31;
                const int idx = (((bb * H_ + h) * N_) + n) * HD_ + d;
                if (which == 0) { v0 *= SCALE; v1 *= SCALE; }
                __half2 hv = __floats2half2_rn(v0, v1);
                if (which == 0)      *(__half2*)&g_qh[idx] = hv;
                else if (which == 1) *(__half2*)&g_kh[idx] = hv;
                else                 *(__half2*)&g_vh[idx] = hv;
            }
        }
    }
}

// ---------------------------------------------------------------------------
// Kernel 2: mma.sync fp16 flash attention. 128 q rows/CTA (32/warp, 2 m-tiles),
//   KV tiles of 64 keys, cp.async double-buffered.
// ---------------------------------------------------------------------------
#define KT 64

__global__ __launch_bounds__(128) void attn_mma_kernel(const float* __restrict__ bt)
{
    __shared__ __align__(16) __half Ks[2][KT][ROWP];
    __shared__ __align__(16) __half Vs[2][KT][ROWP];
    __shared__ float b7s[49];

    const int tid  = threadIdx.x;
    const int lane = tid & 31;
    const int warp = tid >> 5;
    const int bh = blockIdx.y;
    const int q0 = blockIdx.x * 128;
    const long base = (long)bh * N_;

    if (tid < 49) b7s[tid] = bt[(tid / 7) - (tid % 7) + 6];

    const uint32_t ks_base0 = smem_u32(&Ks[0][0][0]);
    const uint32_t vs_base0 = smem_u32(&Vs[0][0][0]);
    const uint32_t kv_stride = KT * ROWP * 2;

    const int r  = lane >> 2;
    const int cq = lane & 3;
    const int c2 = cq * 2;

    int qa7[2], qb7[2];
    uint32_t qf[2][8];
    int qrA[2];
#pragma unroll
    for (int mt = 0; mt < 2; mt++) {
        qrA[mt] = q0 + warp * 32 + mt * 16 + r;
        const int qrB = qrA[mt] + 8;
        qa7[mt] = (qrA[mt] % 7) * 7;
        qb7[mt] = (qrB % 7) * 7;
        const uint32_t* qpA = (const uint32_t*)(g_qh + (base + qrA[mt]) * HD_);
        const uint32_t* qpB = (const uint32_t*)(g_qh + (base + qrB) * HD_);
        qf[mt][0] = qpA[cq];      qf[mt][1] = qpB[cq];
        qf[mt][2] = qpA[cq + 4];  qf[mt][3] = qpB[cq + 4];
        qf[mt][4] = qpA[cq + 8];  qf[mt][5] = qpB[cq + 8];
        qf[mt][6] = qpA[cq + 12]; qf[mt][7] = qpB[cq + 12];
    }

    float oacc[2][4][4];
#pragma unroll
    for (int mt = 0; mt < 2; mt++)
#pragma unroll
        for (int n = 0; n < 4; n++)
#pragma unroll
            for (int i = 0; i < 4; i++) oacc[mt][n][i] = 0.f;
    float lA[2] = {0.f, 0.f}, lB[2] = {0.f, 0.f};

    // staging: row=tid>>1, half=tid&1 (2x16B per tensor per thread)
    const int sj = tid >> 1;
    const int sh = tid & 1;
    const uint32_t s_so = (uint32_t)sj * 80u + (uint32_t)sh * 32u;
    const __half* kgp = g_kh + (base + sj) * HD_ + sh * 16;
    const __half* vgp = g_vh + (base + sj) * HD_ + sh * 16;

#define ATT_STAGE(t, bufn) do { \
        cp16(ks_base0 + (bufn) * kv_stride + s_so +  0, kgp + (long)(t) * HD_);     \
        cp16(ks_base0 + (bufn) * kv_stride + s_so + 16, kgp + (long)(t) * HD_ + 8); \
        cp16(vs_base0 + (bufn) * kv_stride + s_so +  0, vgp + (long)(t) * HD_);     \
        cp16(vs_base0 + (bufn) * kv_stride + s_so + 16, vgp + (long)(t) * HD_ + 8); \
    } while (0)

    ATT_STAGE(0, 0); CP_COMMIT();

    int buf = 0;
#pragma unroll 1
    for (int it = 0; it < N_ / KT; it++) {
        CP_WAIT0();
        __syncthreads();
        if (it < N_ / KT - 1) { ATT_STAGE((it + 1) * KT, buf ^ 1); CP_COMMIT(); }

        const int t = it * KT;
        const uint32_t ks_base = ks_base0 + (uint32_t)buf * kv_stride;
        const uint32_t vs_base = vs_base0 + (uint32_t)buf * kv_stride;

        // ---- S = Q @ K^T, fused bias+exp+pack epilogue per j-tile
        uint32_t ph[8][2][2];
        int jm = (t + c2) % 7;
#pragma unroll
        for (int jt = 0; jt < 8; jt++) {
            uint32_t kf[4];
            uint32_t addr = ks_base + (uint32_t)((jt * 8 + (lane & 7)) * (ROWP * 2))
                          + (uint32_t)((lane >> 3) * 16);
            ldmx4(kf, addr);
            float sa[2][4];
#pragma unroll
            for (int mt = 0; mt < 2; mt++) {
                sa[mt][0] = sa[mt][1] = sa[mt][2] = sa[mt][3] = 0.f;
                mma16816(sa[mt], qf[mt][0], qf[mt][1], qf[mt][2], qf[mt][3], kf[0], kf[1]);
                mma16816(sa[mt], qf[mt][4], qf[mt][5], qf[mt][6], qf[mt][7], kf[2], kf[3]);
            }
            int jm1 = jm + 1; if (jm1 == 7) jm1 = 0;
#pragma unroll
            for (int mt = 0; mt < 2; mt++) {
                float p0 = __expf(sa[mt][0] + b7s[qa7[mt] + jm]);
                float p1 = __expf(sa[mt][1] + b7s[qa7[mt] + jm1]);
                float p2 = __expf(sa[mt][2] + b7s[qb7[mt] + jm]);
                float p3 = __expf(sa[mt][3] + b7s[qb7[mt] + jm1]);
                lA[mt] += p0 + p1;
                lB[mt] += p2 + p3;
                __half2 hA = __floats2half2_rn(p0, p1);
                __half2 hB = __floats2half2_rn(p2, p3);
                ph[jt][mt][0] = *reinterpret_cast<uint32_t*>(&hA);
                ph[jt][mt][1] = *reinterpret_cast<uint32_t*>(&hB);
            }
            jm = jm1;
        }

        // ---- O += P @ V
#pragma unroll
        for (int kt = 0; kt < 4; kt++) {
#pragma unroll
            for (int ntp = 0; ntp < 2; ntp++) {
                uint32_t vf[4];
                uint32_t row = (uint32_t)(kt * 16 + ((lane >> 3) & 1) * 8 + (lane & 7));
                uint32_t col = (uint32_t)(ntp * 16 + (lane >> 4) * 8);
                uint32_t addr = vs_base + row * (ROWP * 2) + col * 2;
                ldmx4t(vf, addr);
#pragma unroll
                for (int mt = 0; mt < 2; mt++) {
                    mma16816(oacc[mt][ntp * 2 + 0],
                             ph[kt * 2][mt][0], ph[kt * 2][mt][1],
                             ph[kt * 2 + 1][mt][0], ph[kt * 2 + 1][mt][1],
                             vf[0], vf[1]);
                    mma16816(oacc[mt][ntp * 2 + 1],
                             ph[kt * 2][mt][0], ph[kt * 2][mt][1],
                             ph[kt * 2 + 1][mt][0], ph[kt * 2 + 1][mt][1],
                             vf[2], vf[3]);
                }
            }
        }
        buf ^= 1;
    }

#pragma unroll
    for (int mt = 0; mt < 2; mt++) {
        float la = lA[mt], lb = lB[mt];
        la += __shfl_xor_sync(0xffffffffu, la, 1);
        la += __shfl_xor_sync(0xffffffffu, la, 2);
        lb += __shfl_xor_sync(0xffffffffu, lb, 1);
        lb += __shfl_xor_sync(0xffffffffu, lb, 2);
        const float invA = 1.f / la;
        const float invB = 1.f / lb;
        __half* opA = g_atth + (base + qrA[mt]) * HD_;
        __half* opB = g_atth + (base + qrA[mt] + 8) * HD_;
#pragma unroll
        for (int nt = 0; nt < 4; nt++) {
            __half2 va = __floats2half2_rn(oacc[mt][nt][0] * invA, oacc[mt][nt][1] * invA);
            __half2 vb = __floats2half2_rn(oacc[mt][nt][2] * invB, oacc[mt][nt][3] * invB);
            *(__half2*)&opA[nt * 8 + c2] = va;
            *(__half2*)&opB[nt * 8 + c2] = vb;
        }
    }
}

// ---------------------------------------------------------------------------
// Kernel 3: proj GEMM via mma.sync, cp.async double-buffered, fp16 inputs.
// ---------------------------------------------------------------------------
__global__ __launch_bounds__(256) void proj_mma_kernel(
    const float* __restrict__ bias, float* __restrict__ out)
{
    __shared__ __align__(16) __half Ah[2][128][ROWP];
    __shared__ __align__(16) __half Bh[2][64][ROWP];

    const int tid  = threadIdx.x;
    const int lane = tid & 31;
    const int warp = tid >> 5;
    const int wm   = warp & 3;
    const int wn   = warp >> 2;
    const int m0   = blockIdx.y * 128;
    const int n0   = blockIdx.x * 64;

    const uint32_t a_base0 = smem_u32(&Ah[0][0][0]);
    const uint32_t b_base0 = smem_u32(&Bh[0][0][0]);
    const uint32_t a_stride = 128 * ROWP * 2;
    const uint32_t b_stride = 64 * ROWP * 2;

    float acc[2][4][4];
#pragma unroll
    for (int mt = 0; mt < 2; mt++)
#pragma unroll
        for (int nt = 0; nt < 4; nt++)
#pragma unroll
            for (int i = 0; i < 4; i++) acc[mt][nt][i] = 0.f;

    const int arow = tid >> 1;
    const int ach  = tid & 1;
    const int brow = tid >> 2;
    const int bch  = tid & 3;
    const uint32_t a_so = (uint32_t)arow * 80u + (uint32_t)ach * 32u;
    const uint32_t b_so = (uint32_t)brow * 80u + (uint32_t)bch * 16u;

    const int m  = m0 + arow;
    const int bb = m >> 11;
    const int nn = m & (N_ - 1);
    const __half* agp = g_atth + ((long)bb * H_ * N_ + nn) * HD_ + ach * 16;
    const __half* bgp = g_pwh + (n0 + brow) * C_ + bch * 8;

    // head h chunk: offset h * N_ * HD_ within this batch; k0 = h*32
#define PROJ_STAGE(h, bufn) do { \
        cp16(a_base0 + (bufn) * a_stride + a_so +  0, agp + (long)(h) * N_ * HD_);     \
        cp16(a_base0 + (bufn) * a_stride + a_so + 16, agp + (long)(h) * N_ * HD_ + 8); \
        cp16(b_base0 + (bufn) * b_stride + b_so,      bgp + (h) * 32);                 \
    } while (0)

    PROJ_STAGE(0, 0); CP_COMMIT();

    int buf = 0;
#pragma unroll
    for (int it = 0; it < 8; it++) {
        CP_WAIT0();
        __syncthreads();
        if (it < 7) { PROJ_STAGE(it + 1, buf ^ 1); CP_COMMIT(); }

        const uint32_t a_base = a_base0 + (uint32_t)buf * a_stride;
        const uint32_t b_base = b_base0 + (uint32_t)buf * b_stride;
        uint32_t bf[4][4];
#pragma unroll
        for (int nt = 0; nt < 4; nt++) {
            uint32_t addr = b_base
                + (uint32_t)((wn * 32 + nt * 8 + (lane & 7)) * (ROWP * 2))
                + (uint32_t)((lane >> 3) * 16);
            ldmx4(bf[nt], addr);
        }
#pragma unroll
        for (int kk = 0; kk < 2; kk++) {
            uint32_t af[2][4];
#pragma unroll
            for (int mt = 0; mt < 2; mt++) {
                uint32_t addr = a_base
                    + (uint32_t)((wm * 32 + mt * 16 + (lane & 15)) * (ROWP * 2))
                    + (uint32_t)((lane >> 4) * 16 + kk * 32);
                ldmx4(af[mt], addr);
            }
#pragma unroll
            for (int mt = 0; mt < 2; mt++)
#pragma unroll
                for (int nt = 0; nt < 4; nt++)
                    mma16816(acc[mt][nt],
                             af[mt][0], af[mt][1], af[mt][2], af[mt][3],
                             bf[nt][kk * 2], bf[nt][kk * 2 + 1]);
        }
        buf ^= 1;
    }

    const int rA = lane >> 2;
    const int c2 = (lane & 3) * 2;
#pragma unroll
    for (int mt = 0; mt < 2; mt++) {
#pragma unroll
        for (int half8 = 0; half8 < 2; half8++) {
            const int mm = m0 + wm * 32 + mt * 16 + half8 * 8 + rA;
#pragma unroll
            for (int nt = 0; nt < 4; nt++) {
                const int o = n0 + wn * 32 + nt * 8 + c2;
                float2 v;
                v.x = acc[mt][nt][half8 * 2 + 0] + bias[o];
                v.y = acc[mt][nt][half8 * 2 + 1] + bias[o + 1];
                *(float2*)&out[mm * C_ + o] = v;
            }
        }
    }
}

// ---------------------------------------------------------------------------
// Launch
// ---------------------------------------------------------------------------
extern "C" void kernel_launch(void* const* d_in, const int* in_sizes, int n_in,
                              void* d_out, int out_size)
{
    const float* x      = (const float*)d_in[0];
    const float* qkv_w  = (const float*)d_in[1];
    const float* qkv_b  = (const float*)d_in[2];
    const float* proj_w = (const float*)d_in[3];
    const float* proj_b = (const float*)d_in[4];
    const float* btab   = (const float*)d_in[5];
    float* out = (float*)d_out;

    (void)in_sizes; (void)n_in; (void)out_size;

    conv_kernel<<<(XE + WE + PE) / (256 * 4), 256>>>(x, qkv_w, proj_w);

    dim3 g1(QKV_OUT / 64, M_ / 128);       // (12, 64)
    qkv_mma_kernel<<<g1, 256>>>(qkv_b);

    dim3 g2(N_ / 128, B_ * H_);            // (16, 32)
    attn_mma_kernel<<<g2, 128>>>(btab);

    dim3 g3(C_ / 64, M_ / 128);            // (4, 64)
    proj_mma_kernel<<<g3, 256>>>(proj_b, out);
}